// round 1
// baseline (speedup 1.0000x reference)
#include <cuda_runtime.h>

#define BB   2
#define SS   2048
#define DD   1024
#define HH   16
#define DKK  64
#define MROWS (BB*SS)   // 4096

// ---------------- scratch (static device globals; no allocation) ----------------
__device__ float g_Q[BB*HH*SS*DKK];   // [B,H,S,DK]
__device__ float g_K[BB*HH*SS*DKK];
__device__ float g_V[BB*HH*SS*DKK];
__device__ float g_ctx[MROWS*DD];     // [B*S, D]

// ---------------- fp32 SGEMM: C = A[M,K] @ W[K,N] + bias ----------------
// M=4096, N=K=1024 fixed. BM=BN=128, BK=8, TM=TN=8, 256 threads.
// SPLIT_HEADS epilogue writes to [B,H,S,DK] layout instead of [M,N].
template <bool SPLIT_HEADS>
__global__ __launch_bounds__(256) void sgemm_bias(
    const float* __restrict__ A, const float* __restrict__ W,
    const float* __restrict__ bias, float* __restrict__ C)
{
    constexpr int M = MROWS, N = DD, K = DD;
    constexpr int BM = 128, BN = 128, BK = 8, TM = 8, TN = 8;
    __shared__ float As[BK][BM];
    __shared__ float Bs[BK][BN];

    const int tid  = threadIdx.x;
    const int tr   = tid / 16;          // 0..15 (row of 8x8 tile)
    const int tc   = tid % 16;          // 0..15 (col of 8x8 tile)
    const int brow = blockIdx.y;
    const int bcol = blockIdx.x;

    const float* Ab = A + (size_t)brow * BM * K;
    const float* Wb = W + (size_t)bcol * BN;

    // A-tile load map: 128 rows x 8 k; each thread: one float4 (row aRow, k aCol..aCol+3)
    const int aRow = tid >> 1;          // 0..127
    const int aCol = (tid & 1) * 4;     // 0 or 4
    // B-tile load map: 8 k x 128 cols; each thread: one float4 along N
    const int bRow = tid >> 5;          // 0..7
    const int bCol = (tid & 31) * 4;    // 0..124

    float acc[TM][TN];
    #pragma unroll
    for (int i = 0; i < TM; ++i)
        #pragma unroll
        for (int j = 0; j < TN; ++j) acc[i][j] = 0.f;

    for (int k0 = 0; k0 < K; k0 += BK) {
        float4 av = *(const float4*)(Ab + (size_t)aRow * K + k0 + aCol);
        As[aCol + 0][aRow] = av.x;
        As[aCol + 1][aRow] = av.y;
        As[aCol + 2][aRow] = av.z;
        As[aCol + 3][aRow] = av.w;
        float4 bv = *(const float4*)(Wb + (size_t)(k0 + bRow) * N + bCol);
        *(float4*)&Bs[bRow][bCol] = bv;
        __syncthreads();

        #pragma unroll
        for (int k = 0; k < BK; ++k) {
            float ra[TM], rb[TN];
            #pragma unroll
            for (int i = 0; i < TM; i += 4) {
                float4 t4 = *(const float4*)&As[k][tr * TM + i];
                ra[i] = t4.x; ra[i+1] = t4.y; ra[i+2] = t4.z; ra[i+3] = t4.w;
            }
            #pragma unroll
            for (int j = 0; j < TN; j += 4) {
                float4 t4 = *(const float4*)&Bs[k][tc * TN + j];
                rb[j] = t4.x; rb[j+1] = t4.y; rb[j+2] = t4.z; rb[j+3] = t4.w;
            }
            #pragma unroll
            for (int i = 0; i < TM; ++i)
                #pragma unroll
                for (int j = 0; j < TN; ++j)
                    acc[i][j] += ra[i] * rb[j];
        }
        __syncthreads();
    }

    // epilogue
    #pragma unroll
    for (int i = 0; i < TM; ++i) {
        int row = brow * BM + tr * TM + i;           // 0..M-1
        #pragma unroll
        for (int j = 0; j < TN; ++j) {
            int col = bcol * BN + tc * TN + j;       // 0..N-1
            float v = acc[i][j] + bias[col];
            if (SPLIT_HEADS) {
                int b  = row / SS, s = row % SS;
                int h  = col / DKK, dk = col % DKK;
                C[(((size_t)(b * HH + h) * SS) + s) * DKK + dk] = v;
            } else {
                C[(size_t)row * N + col] = v;
            }
        }
    }
}

// ---------------- causal flash attention (fp32) ----------------
// Q,K,V: [B*H, S, DK]. ctx out: [B*S, D] with head-interleave.
// 1 thread = 1 query row. BM=128 rows/block, K/V tiles of BN=64 via smem.
__global__ __launch_bounds__(128) void attn_kernel(
    const float* __restrict__ Q, const float* __restrict__ K,
    const float* __restrict__ V, float* __restrict__ ctx)
{
    constexpr int BM = 128, BN = 64;
    __shared__ float Ks[BN][DKK];
    __shared__ float Vs[BN][DKK];

    const int bh = blockIdx.y;                 // 0..B*H-1
    const int q0 = blockIdx.x * BM;
    const int t  = threadIdx.x;                // 0..127
    const int qi = q0 + t;

    // load this thread's query row into registers
    float qreg[DKK];
    {
        const float4* Q4 = (const float4*)(Q + ((size_t)bh * SS + qi) * DKK);
        #pragma unroll
        for (int d4 = 0; d4 < DKK / 4; ++d4) {
            float4 v4 = Q4[d4];
            qreg[4*d4+0] = v4.x; qreg[4*d4+1] = v4.y;
            qreg[4*d4+2] = v4.z; qreg[4*d4+3] = v4.w;
        }
    }

    float acc[DKK];
    #pragma unroll
    for (int d = 0; d < DKK; ++d) acc[d] = 0.f;
    float m = -1e30f, l = 0.f;
    const float scale = 0.125f;   // 1/sqrt(64)

    for (int ts = 0; ts < q0 + BM; ts += BN) {
        // stage K/V tile (coalesced float4 copies)
        const float4* Kt = (const float4*)(K + ((size_t)bh * SS + ts) * DKK);
        const float4* Vt = (const float4*)(V + ((size_t)bh * SS + ts) * DKK);
        float4* Ks4 = (float4*)Ks;
        float4* Vs4 = (float4*)Vs;
        #pragma unroll
        for (int i = t; i < BN * DKK / 4; i += BM) {
            Ks4[i] = Kt[i];
            Vs4[i] = Vt[i];
        }
        __syncthreads();

        const int jmax = min(BN, qi - ts + 1);   // causal bound (may be <=0)
        for (int j = 0; j < jmax; ++j) {
            float s = 0.f;
            #pragma unroll
            for (int d = 0; d < DKK; ++d) s += qreg[d] * Ks[j][d];
            s *= scale;
            if (s > m) {                       // rare rescale path
                float corr = __expf(m - s);
                m = s;
                l *= corr;
                #pragma unroll
                for (int d = 0; d < DKK; ++d) acc[d] *= corr;
            }
            float p = __expf(s - m);
            l += p;
            #pragma unroll
            for (int d = 0; d < DKK; ++d) acc[d] += p * Vs[j][d];
        }
        __syncthreads();
    }

    const float inv = 1.f / l;
    const int b = bh / HH, h = bh % HH;
    float* out = ctx + ((size_t)(b * SS + qi) * DD) + h * DKK;
    #pragma unroll
    for (int d = 0; d < DKK; d += 4) {
        float4 v4 = make_float4(acc[d] * inv, acc[d+1] * inv,
                                acc[d+2] * inv, acc[d+3] * inv);
        *(float4*)(out + d) = v4;
    }
}

// ---------------- launch ----------------
extern "C" void kernel_launch(void* const* d_in, const int* in_sizes, int n_in,
                              void* d_out, int out_size)
{
    const float* q  = (const float*)d_in[0];
    const float* k  = (const float*)d_in[1];
    const float* v  = (const float*)d_in[2];
    // d_in[3] = mask (causal tril) — implemented analytically
    const float* wq = (const float*)d_in[4];
    const float* bq = (const float*)d_in[5];
    const float* wk = (const float*)d_in[6];
    const float* bk = (const float*)d_in[7];
    const float* wv = (const float*)d_in[8];
    const float* bv = (const float*)d_in[9];
    const float* wo = (const float*)d_in[10];
    const float* bo = (const float*)d_in[11];

    float *Qp, *Kp, *Vp, *Cp;
    cudaGetSymbolAddress((void**)&Qp, g_Q);
    cudaGetSymbolAddress((void**)&Kp, g_K);
    cudaGetSymbolAddress((void**)&Vp, g_V);
    cudaGetSymbolAddress((void**)&Cp, g_ctx);

    dim3 gg(DD / 128, MROWS / 128);   // (8, 32)
    dim3 gb(256);
    sgemm_bias<true><<<gg, gb>>>(q, wq, bq, Qp);
    sgemm_bias<true><<<gg, gb>>>(k, wk, bk, Kp);
    sgemm_bias<true><<<gg, gb>>>(v, wv, bv, Vp);

    attn_kernel<<<dim3(SS / 128, BB * HH), 128>>>(Qp, Kp, Vp, Cp);

    sgemm_bias<false><<<gg, gb>>>(Cp, wo, bo, (float*)d_out);
}

// round 5
// speedup vs baseline: 1.3959x; 1.3959x over previous
#include <cuda_runtime.h>
#include <cstdint>

#define BB   2
#define SS   2048
#define DD   1024
#define HH   16
#define DKK  64
#define MROWS (BB*SS)   // 4096

// ---------------- scratch (static device globals; no allocation) ----------------
__device__ float g_Q[BB*HH*SS*DKK];   // [B,H,S,DK]
__device__ float g_K[BB*HH*SS*DKK];
__device__ float g_V[BB*HH*SS*DKK];
__device__ float g_ctx[MROWS*DD];     // [B*S, D]

// ---------------- helpers: packed f32x2 ----------------
__device__ __forceinline__ unsigned long long pack2(float lo, float hi) {
    unsigned long long r;
    asm("mov.b64 %0, {%1, %2};" : "=l"(r) : "f"(lo), "f"(hi));
    return r;
}
__device__ __forceinline__ void unpack2(unsigned long long v, float& lo, float& hi) {
    asm("mov.b64 {%0, %1}, %2;" : "=f"(lo), "=f"(hi) : "l"(v));
}
__device__ __forceinline__ unsigned long long fma2_(unsigned long long a,
                                                    unsigned long long b,
                                                    unsigned long long c) {
    unsigned long long d;
    asm("fma.rn.f32x2 %0, %1, %2, %3;" : "=l"(d) : "l"(a), "l"(b), "l"(c));
    return d;
}
__device__ __forceinline__ unsigned long long mul2_(unsigned long long a,
                                                    unsigned long long b) {
    unsigned long long d;
    asm("mul.rn.f32x2 %0, %1, %2;" : "=l"(d) : "l"(a), "l"(b));
    return d;
}
__device__ __forceinline__ uint32_t f2tf32(float f) {
    uint32_t r;
    asm("cvt.rna.tf32.f32 %0, %1;" : "=r"(r) : "f"(f));
    return r;
}

// ---------------- tf32 tensor-core GEMM: C = A[M,K] @ W[K,N] + bias ----------------
// M=4096, N=K=1024. BM=BN=128, BK=16. 256 threads = 8 warps (2x4); warp tile 64x32.
// mma.sync.aligned.m16n8k8.row.col.f32.tf32.tf32.f32
template <bool SPLIT_HEADS>
__global__ __launch_bounds__(256) void gemm_tf32(
    const float* __restrict__ A, const float* __restrict__ W,
    const float* __restrict__ bias, float* __restrict__ C)
{
    constexpr int N = DD, K = DD;
    constexpr int BM = 128, BN = 128, BK = 16;
    __shared__ float As[BK][BM + 8];   // [k][m], pad 8 -> conflict-free frag loads
    __shared__ float Bs[BK][BN + 8];   // [k][n]

    const int tid  = threadIdx.x;
    const int warp = tid >> 5;
    const int lane = tid & 31;
    const int gid  = lane >> 2;        // 0..7
    const int tg   = lane & 3;         // 0..3
    const int wm   = warp >> 2;        // 0..1 (64-row slab)
    const int wn   = warp & 3;         // 0..3 (32-col slab)
    const int brow = blockIdx.y;
    const int bcol = blockIdx.x;

    const float* Ab = A + (size_t)brow * BM * K;
    const float* Wb = W + (size_t)bcol * BN;

    float c[4][4][4];
    #pragma unroll
    for (int mt = 0; mt < 4; ++mt)
        #pragma unroll
        for (int nt = 0; nt < 4; ++nt)
            #pragma unroll
            for (int i = 0; i < 4; ++i) c[mt][nt][i] = 0.f;

    for (int k0 = 0; k0 < K; k0 += BK) {
        // stage A tile: 128 rows x 16 k = 512 float4; 2 per thread
        #pragma unroll
        for (int r = 0; r < 2; ++r) {
            int f4 = tid + r * 256;
            int row = f4 >> 2;           // 0..127
            int kc  = (f4 & 3) * 4;      // 0,4,8,12
            float4 av = *(const float4*)(Ab + (size_t)row * K + k0 + kc);
            As[kc + 0][row] = __uint_as_float(f2tf32(av.x));
            As[kc + 1][row] = __uint_as_float(f2tf32(av.y));
            As[kc + 2][row] = __uint_as_float(f2tf32(av.z));
            As[kc + 3][row] = __uint_as_float(f2tf32(av.w));
        }
        // stage B tile: 16 k x 128 n = 512 float4; 2 per thread
        #pragma unroll
        for (int r = 0; r < 2; ++r) {
            int f4 = tid + r * 256;
            int kr = f4 >> 5;            // 0..15
            int nc = (f4 & 31) * 4;      // 0..124
            float4 bv = *(const float4*)(Wb + (size_t)(k0 + kr) * N + nc);
            Bs[kr][nc + 0] = __uint_as_float(f2tf32(bv.x));
            Bs[kr][nc + 1] = __uint_as_float(f2tf32(bv.y));
            Bs[kr][nc + 2] = __uint_as_float(f2tf32(bv.z));
            Bs[kr][nc + 3] = __uint_as_float(f2tf32(bv.w));
        }
        __syncthreads();

        #pragma unroll
        for (int kk = 0; kk < BK; kk += 8) {
            uint32_t a[4][4], b[4][2];
            #pragma unroll
            for (int mt = 0; mt < 4; ++mt) {
                int m0 = wm * 64 + mt * 16;
                a[mt][0] = __float_as_uint(As[kk + tg    ][m0 + gid    ]);
                a[mt][1] = __float_as_uint(As[kk + tg    ][m0 + gid + 8]);
                a[mt][2] = __float_as_uint(As[kk + tg + 4][m0 + gid    ]);
                a[mt][3] = __float_as_uint(As[kk + tg + 4][m0 + gid + 8]);
            }
            #pragma unroll
            for (int nt = 0; nt < 4; ++nt) {
                int n0 = wn * 32 + nt * 8;
                b[nt][0] = __float_as_uint(Bs[kk + tg    ][n0 + gid]);
                b[nt][1] = __float_as_uint(Bs[kk + tg + 4][n0 + gid]);
            }
            #pragma unroll
            for (int mt = 0; mt < 4; ++mt)
                #pragma unroll
                for (int nt = 0; nt < 4; ++nt) {
                    asm volatile(
                        "mma.sync.aligned.m16n8k8.row.col.f32.tf32.tf32.f32 "
                        "{%0,%1,%2,%3}, {%4,%5,%6,%7}, {%8,%9}, {%0,%1,%2,%3};"
                        : "+f"(c[mt][nt][0]), "+f"(c[mt][nt][1]),
                          "+f"(c[mt][nt][2]), "+f"(c[mt][nt][3])
                        : "r"(a[mt][0]), "r"(a[mt][1]), "r"(a[mt][2]), "r"(a[mt][3]),
                          "r"(b[nt][0]), "r"(b[nt][1]));
                }
        }
        __syncthreads();
    }

    // epilogue: c[mt][nt] maps to rows {r0, r0+8}, cols {c0, c0+1}
    #pragma unroll
    for (int mt = 0; mt < 4; ++mt) {
        #pragma unroll
        for (int nt = 0; nt < 4; ++nt) {
            int r0 = brow * BM + wm * 64 + mt * 16 + gid;
            int cc = bcol * BN + wn * 32 + nt * 8 + tg * 2;
            #pragma unroll
            for (int i = 0; i < 4; ++i) {
                int row = r0 + (i >> 1) * 8;
                int col = cc + (i & 1);
                float v = c[mt][nt][i] + bias[col];
                if (SPLIT_HEADS) {
                    int b_  = row / SS, s = row % SS;
                    int h   = col / DKK, dk = col % DKK;
                    C[(((size_t)(b_ * HH + h) * SS) + s) * DKK + dk] = v;
                } else {
                    C[(size_t)row * N + col] = v;
                }
            }
        }
    }
}

// ---------------- causal flash attention (fp32, packed f32x2 math) ----------------
// Q,K,V: [B*H, S, DK]. ctx out: [B*S, D] with head-interleave.
// 1 thread = 1 query row. BM=128 rows/block, K/V tiles of BN=64 via smem.
__global__ __launch_bounds__(128) void attn_kernel(
    const float* __restrict__ Q, const float* __restrict__ K,
    const float* __restrict__ V, float* __restrict__ ctx)
{
    constexpr int BM = 128, BN = 64;
    __shared__ __align__(16) float Ks[BN][DKK];
    __shared__ __align__(16) float Vs[BN][DKK];

    const int bh = blockIdx.y;                 // 0..B*H-1
    const int q0 = blockIdx.x * BM;
    const int t  = threadIdx.x;                // 0..127
    const int qi = q0 + t;

    // load query row, packed into f32x2
    unsigned long long q2[DKK / 2];
    {
        const float4* Q4 = (const float4*)(Q + ((size_t)bh * SS + qi) * DKK);
        #pragma unroll
        for (int i = 0; i < DKK / 4; ++i) {
            float4 v4 = Q4[i];
            q2[2 * i + 0] = pack2(v4.x, v4.y);
            q2[2 * i + 1] = pack2(v4.z, v4.w);
        }
    }

    unsigned long long acc2[DKK / 2];
    #pragma unroll
    for (int i = 0; i < DKK / 2; ++i) acc2[i] = 0ull;
    float m = -1e30f, l = 0.f;
    const float scale = 0.125f;   // 1/sqrt(64)

    for (int ts = 0; ts < q0 + BM; ts += BN) {
        // stage K/V tile (coalesced float4 copies)
        const float4* Kt = (const float4*)(K + ((size_t)bh * SS + ts) * DKK);
        const float4* Vt = (const float4*)(V + ((size_t)bh * SS + ts) * DKK);
        float4* Ks4 = (float4*)Ks;
        float4* Vs4 = (float4*)Vs;
        #pragma unroll
        for (int i = t; i < BN * DKK / 4; i += BM) {
            Ks4[i] = Kt[i];
            Vs4[i] = Vt[i];
        }
        __syncthreads();

        const int jmax = min(BN, qi - ts + 1);   // causal bound (may be <=0)
        for (int j = 0; j < jmax; ++j) {
            // dot(q, K[j]) with 4 independent f32x2 chains
            const ulonglong2* Krow = (const ulonglong2*)(&Ks[j][0]);
            unsigned long long s2a = 0ull, s2b = 0ull, s2c = 0ull, s2d = 0ull;
            #pragma unroll
            for (int i = 0; i < DKK / 4; i += 2) {
                ulonglong2 kk0 = Krow[i];
                ulonglong2 kk1 = Krow[i + 1];
                s2a = fma2_(q2[2 * i + 0], kk0.x, s2a);
                s2b = fma2_(q2[2 * i + 1], kk0.y, s2b);
                s2c = fma2_(q2[2 * i + 2], kk1.x, s2c);
                s2d = fma2_(q2[2 * i + 3], kk1.y, s2d);
            }
            float xa, xb, xc, xd, ya, yb, yc, yd;
            unpack2(s2a, xa, ya); unpack2(s2b, xb, yb);
            unpack2(s2c, xc, yc); unpack2(s2d, xd, yd);
            float s = ((xa + ya) + (xb + yb)) + ((xc + yc) + (xd + yd));
            s *= scale;

            if (s > m) {                       // rare rescale path
                float corr = __expf(m - s);
                m = s;
                l *= corr;
                unsigned long long corr2 = pack2(corr, corr);
                #pragma unroll
                for (int i = 0; i < DKK / 2; ++i) acc2[i] = mul2_(acc2[i], corr2);
            }
            float p = __expf(s - m);
            l += p;
            unsigned long long p2 = pack2(p, p);
            const ulonglong2* Vrow = (const ulonglong2*)(&Vs[j][0]);
            #pragma unroll
            for (int i = 0; i < DKK / 4; ++i) {
                ulonglong2 vv = Vrow[i];
                acc2[2 * i + 0] = fma2_(p2, vv.x, acc2[2 * i + 0]);
                acc2[2 * i + 1] = fma2_(p2, vv.y, acc2[2 * i + 1]);
            }
        }
        __syncthreads();
    }

    const float inv = 1.f / l;
    const int b = bh / HH, h = bh % HH;
    float* out = ctx + ((size_t)(b * SS + qi) * DD) + h * DKK;
    #pragma unroll
    for (int i = 0; i < DKK / 4; ++i) {
        float lo0, hi0, lo1, hi1;
        unpack2(acc2[2 * i + 0], lo0, hi0);
        unpack2(acc2[2 * i + 1], lo1, hi1);
        float4 v4 = make_float4(lo0 * inv, hi0 * inv, lo1 * inv, hi1 * inv);
        *(float4*)(out + 4 * i) = v4;
    }
}

// ---------------- launch ----------------
extern "C" void kernel_launch(void* const* d_in, const int* in_sizes, int n_in,
                              void* d_out, int out_size)
{
    const float* q  = (const float*)d_in[0];
    const float* k  = (const float*)d_in[1];
    const float* v  = (const float*)d_in[2];
    // d_in[3] = mask (causal tril) — implemented analytically
    const float* wq = (const float*)d_in[4];
    const float* bq = (const float*)d_in[5];
    const float* wk = (const float*)d_in[6];
    const float* bk = (const float*)d_in[7];
    const float* wv = (const float*)d_in[8];
    const float* bv = (const float*)d_in[9];
    const float* wo = (const float*)d_in[10];
    const float* bo = (const float*)d_in[11];

    float *Qp, *Kp, *Vp, *Cp;
    cudaGetSymbolAddress((void**)&Qp, g_Q);
    cudaGetSymbolAddress((void**)&Kp, g_K);
    cudaGetSymbolAddress((void**)&Vp, g_V);
    cudaGetSymbolAddress((void**)&Cp, g_ctx);

    dim3 gg(DD / 128, MROWS / 128);   // (8, 32)
    dim3 gb(256);
    gemm_tf32<true><<<gg, gb>>>(q, wq, bq, Qp);
    gemm_tf32<true><<<gg, gb>>>(k, wk, bk, Kp);
    gemm_tf32<true><<<gg, gb>>>(v, wv, bv, Vp);

    attn_kernel<<<dim3(SS / 128, BB * HH), 128>>>(Qp, Kp, Vp, Cp);

    gemm_tf32<false><<<gg, gb>>>(Cp, wo, bo, (float*)d_out);
}

// round 9
// speedup vs baseline: 3.3014x; 2.3650x over previous
#include <cuda_runtime.h>
#include <cstdint>

#define BB   2
#define SS   2048
#define DD   1024
#define HH   16
#define DKK  64
#define MROWS (BB*SS)   // 4096

// ---------------- scratch (static device globals; no allocation) ----------------
__device__ float g_Q[BB*HH*SS*DKK];   // [B,H,S,DK]
__device__ float g_K[BB*HH*SS*DKK];
__device__ float g_V[BB*HH*SS*DKK];
__device__ float g_ctx[MROWS*DD];     // [B*S, D]

__device__ __forceinline__ uint32_t f2tf32(float f) {
    uint32_t r;
    asm("cvt.rna.tf32.f32 %0, %1;" : "=r"(r) : "f"(f));
    return r;
}

__device__ __forceinline__ void mma_tf32(float c[4], const uint32_t a[4],
                                         uint32_t b0, uint32_t b1) {
    asm volatile(
        "mma.sync.aligned.m16n8k8.row.col.f32.tf32.tf32.f32 "
        "{%0,%1,%2,%3}, {%4,%5,%6,%7}, {%8,%9}, {%0,%1,%2,%3};"
        : "+f"(c[0]), "+f"(c[1]), "+f"(c[2]), "+f"(c[3])
        : "r"(a[0]), "r"(a[1]), "r"(a[2]), "r"(a[3]), "r"(b0), "r"(b1));
}

// ---------------- tf32 tensor-core GEMM: C = A[M,K] @ W[K,N] + bias ----------------
template <bool SPLIT_HEADS>
__global__ __launch_bounds__(256) void gemm_tf32(
    const float* __restrict__ A, const float* __restrict__ W,
    const float* __restrict__ bias, float* __restrict__ C)
{
    constexpr int N = DD, K = DD;
    constexpr int BM = 128, BN = 128, BK = 16;
    __shared__ float As[BK][BM + 8];
    __shared__ float Bs[BK][BN + 8];

    const int tid  = threadIdx.x;
    const int warp = tid >> 5;
    const int lane = tid & 31;
    const int gid  = lane >> 2;
    const int tg   = lane & 3;
    const int wm   = warp >> 2;
    const int wn   = warp & 3;
    const int brow = blockIdx.y;
    const int bcol = blockIdx.x;

    const float* Ab = A + (size_t)brow * BM * K;
    const float* Wb = W + (size_t)bcol * BN;

    float c[4][4][4];
    #pragma unroll
    for (int mt = 0; mt < 4; ++mt)
        #pragma unroll
        for (int nt = 0; nt < 4; ++nt)
            #pragma unroll
            for (int i = 0; i < 4; ++i) c[mt][nt][i] = 0.f;

    for (int k0 = 0; k0 < K; k0 += BK) {
        #pragma unroll
        for (int r = 0; r < 2; ++r) {
            int f4 = tid + r * 256;
            int row = f4 >> 2;
            int kc  = (f4 & 3) * 4;
            float4 av = *(const float4*)(Ab + (size_t)row * K + k0 + kc);
            As[kc + 0][row] = __uint_as_float(f2tf32(av.x));
            As[kc + 1][row] = __uint_as_float(f2tf32(av.y));
            As[kc + 2][row] = __uint_as_float(f2tf32(av.z));
            As[kc + 3][row] = __uint_as_float(f2tf32(av.w));
        }
        #pragma unroll
        for (int r = 0; r < 2; ++r) {
            int f4 = tid + r * 256;
            int kr = f4 >> 5;
            int nc = (f4 & 31) * 4;
            float4 bv = *(const float4*)(Wb + (size_t)(k0 + kr) * N + nc);
            Bs[kr][nc + 0] = __uint_as_float(f2tf32(bv.x));
            Bs[kr][nc + 1] = __uint_as_float(f2tf32(bv.y));
            Bs[kr][nc + 2] = __uint_as_float(f2tf32(bv.z));
            Bs[kr][nc + 3] = __uint_as_float(f2tf32(bv.w));
        }
        __syncthreads();

        #pragma unroll
        for (int kk = 0; kk < BK; kk += 8) {
            uint32_t a[4][4], b[4][2];
            #pragma unroll
            for (int mt = 0; mt < 4; ++mt) {
                int m0 = wm * 64 + mt * 16;
                a[mt][0] = __float_as_uint(As[kk + tg    ][m0 + gid    ]);
                a[mt][1] = __float_as_uint(As[kk + tg    ][m0 + gid + 8]);
                a[mt][2] = __float_as_uint(As[kk + tg + 4][m0 + gid    ]);
                a[mt][3] = __float_as_uint(As[kk + tg + 4][m0 + gid + 8]);
            }
            #pragma unroll
            for (int nt = 0; nt < 4; ++nt) {
                int n0 = wn * 32 + nt * 8;
                b[nt][0] = __float_as_uint(Bs[kk + tg    ][n0 + gid]);
                b[nt][1] = __float_as_uint(Bs[kk + tg + 4][n0 + gid]);
            }
            #pragma unroll
            for (int mt = 0; mt < 4; ++mt)
                #pragma unroll
                for (int nt = 0; nt < 4; ++nt)
                    mma_tf32(c[mt][nt], a[mt], b[nt][0], b[nt][1]);
        }
        __syncthreads();
    }

    #pragma unroll
    for (int mt = 0; mt < 4; ++mt) {
        #pragma unroll
        for (int nt = 0; nt < 4; ++nt) {
            int r0 = brow * BM + wm * 64 + mt * 16 + gid;
            int cc = bcol * BN + wn * 32 + nt * 8 + tg * 2;
            #pragma unroll
            for (int i = 0; i < 4; ++i) {
                int row = r0 + (i >> 1) * 8;
                int col = cc + (i & 1);
                float v = c[mt][nt][i] + bias[col];
                if (SPLIT_HEADS) {
                    int b_  = row / SS, s = row % SS;
                    int h   = col / DKK, dk = col % DKK;
                    C[(((size_t)(b_ * HH + h) * SS) + s) * DKK + dk] = v;
                } else {
                    C[(size_t)row * N + col] = v;
                }
            }
        }
    }
}

// ---------------- tensor-core causal flash attention (tf32 mma) ----------------
// Block: 64 q-rows of one (b,h); 4 warps x 16 rows. K/V tiles of 64 keys via smem.
// smem strides chosen for conflict-free fragment LDS:
//   Ks stride 68 (QK^T B-frag: bank = 4*gid+tg, distinct)
//   Vs stride 72 (PV   B-frag: bank = 8*tg+gid, distinct)
//   QP stride 68 (Q stage / P slab: bank = 4*gid+tg, distinct)
#define SK 68
#define SV 72
#define ATTN_SMEM ((64*SK + 64*SV + 64*SK) * 4)

__global__ __launch_bounds__(128) void attn_mma(
    const float* __restrict__ Q, const float* __restrict__ K,
    const float* __restrict__ V, float* __restrict__ ctx)
{
    extern __shared__ float sm[];
    float* Ks = sm;                   // [64][SK]
    float* Vs = sm + 64 * SK;         // [64][SV]
    float* QP = sm + 64 * SK + 64 * SV;  // Q stage [64][SK], then P slabs

    const int bh   = blockIdx.y;
    const int q0   = (gridDim.x - 1 - blockIdx.x) * 64;   // heavy blocks first
    const int tid  = threadIdx.x;
    const int w    = tid >> 5;
    const int lane = tid & 31;
    const int gid  = lane >> 2;
    const int tg   = lane & 3;
    const int b    = bh / HH;
    const int h    = bh % HH;
    const size_t base = (size_t)bh * SS * DKK;

    // ---- stage Q tile, build register fragments (scale folded) ----
    for (int i = tid; i < 64 * 16; i += 128) {
        int r = i >> 4, c4 = (i & 15) * 4;
        *(float4*)&QP[r * SK + c4] =
            *(const float4*)(Q + base + (size_t)(q0 + r) * DKK + c4);
    }
    __syncthreads();

    const int m_lo = w * 16 + gid;        // local row (c0/c1)
    uint32_t qf[8][4];
    #pragma unroll
    for (int kc = 0; kc < 8; ++kc) {
        qf[kc][0] = f2tf32(0.125f * QP[(m_lo    ) * SK + kc * 8 + tg    ]);
        qf[kc][1] = f2tf32(0.125f * QP[(m_lo + 8) * SK + kc * 8 + tg    ]);
        qf[kc][2] = f2tf32(0.125f * QP[(m_lo    ) * SK + kc * 8 + tg + 4]);
        qf[kc][3] = f2tf32(0.125f * QP[(m_lo + 8) * SK + kc * 8 + tg + 4]);
    }

    float* Ps = QP + w * (16 * SK);       // warp-private P slab [16][SK]

    float oacc[8][4];
    #pragma unroll
    for (int nt = 0; nt < 8; ++nt)
        #pragma unroll
        for (int i = 0; i < 4; ++i) oacc[nt][i] = 0.f;
    float m_lo_r = -1e30f, m_hi_r = -1e30f;
    float l_lo = 0.f, l_hi = 0.f;

    const int row_lo_g = q0 + m_lo;
    const int row_hi_g = row_lo_g + 8;

    for (int ts = 0; ts <= q0; ts += 64) {
        // ---- stage K,V tiles (tf32-rounded) ----
        for (int i = tid; i < 64 * 16; i += 128) {
            int r = i >> 4, c4 = (i & 15) * 4;
            float4 kv = *(const float4*)(K + base + (size_t)(ts + r) * DKK + c4);
            float4 vv = *(const float4*)(V + base + (size_t)(ts + r) * DKK + c4);
            kv.x = __uint_as_float(f2tf32(kv.x)); kv.y = __uint_as_float(f2tf32(kv.y));
            kv.z = __uint_as_float(f2tf32(kv.z)); kv.w = __uint_as_float(f2tf32(kv.w));
            vv.x = __uint_as_float(f2tf32(vv.x)); vv.y = __uint_as_float(f2tf32(vv.y));
            vv.z = __uint_as_float(f2tf32(vv.z)); vv.w = __uint_as_float(f2tf32(vv.w));
            *(float4*)&Ks[r * SK + c4] = kv;
            *(float4*)&Vs[r * SV + c4] = vv;
        }
        __syncthreads();

        // ---- scores: S = Q K^T ----
        float sf[8][4];
        #pragma unroll
        for (int nt = 0; nt < 8; ++nt)
            #pragma unroll
            for (int i = 0; i < 4; ++i) sf[nt][i] = 0.f;

        #pragma unroll
        for (int kc = 0; kc < 8; ++kc) {
            #pragma unroll
            for (int nt = 0; nt < 8; ++nt) {
                uint32_t b0 = __float_as_uint(Ks[(nt * 8 + gid) * SK + kc * 8 + tg    ]);
                uint32_t b1 = __float_as_uint(Ks[(nt * 8 + gid) * SK + kc * 8 + tg + 4]);
                mma_tf32(sf[nt], qf[kc], b0, b1);
            }
        }

        // ---- causal mask (only diagonal tile has future keys) ----
        if (ts == q0) {
            #pragma unroll
            for (int nt = 0; nt < 8; ++nt) {
                int col = ts + nt * 8 + 2 * tg;
                if (col     > row_lo_g) sf[nt][0] = -1e30f;
                if (col + 1 > row_lo_g) sf[nt][1] = -1e30f;
                if (col     > row_hi_g) sf[nt][2] = -1e30f;
                if (col + 1 > row_hi_g) sf[nt][3] = -1e30f;
            }
        }

        // ---- online softmax ----
        float tmax_lo = -1e30f, tmax_hi = -1e30f;
        #pragma unroll
        for (int nt = 0; nt < 8; ++nt) {
            tmax_lo = fmaxf(tmax_lo, fmaxf(sf[nt][0], sf[nt][1]));
            tmax_hi = fmaxf(tmax_hi, fmaxf(sf[nt][2], sf[nt][3]));
        }
        tmax_lo = fmaxf(tmax_lo, __shfl_xor_sync(0xffffffffu, tmax_lo, 1));
        tmax_lo = fmaxf(tmax_lo, __shfl_xor_sync(0xffffffffu, tmax_lo, 2));
        tmax_hi = fmaxf(tmax_hi, __shfl_xor_sync(0xffffffffu, tmax_hi, 1));
        tmax_hi = fmaxf(tmax_hi, __shfl_xor_sync(0xffffffffu, tmax_hi, 2));

        float mnew_lo = fmaxf(m_lo_r, tmax_lo);
        float mnew_hi = fmaxf(m_hi_r, tmax_hi);
        float corr_lo = __expf(m_lo_r - mnew_lo);
        float corr_hi = __expf(m_hi_r - mnew_hi);
        m_lo_r = mnew_lo; m_hi_r = mnew_hi;

        float psum_lo = 0.f, psum_hi = 0.f;
        #pragma unroll
        for (int nt = 0; nt < 8; ++nt) {
            float p0 = __expf(sf[nt][0] - mnew_lo);
            float p1 = __expf(sf[nt][1] - mnew_lo);
            float p2 = __expf(sf[nt][2] - mnew_hi);
            float p3 = __expf(sf[nt][3] - mnew_hi);
            psum_lo += p0 + p1;
            psum_hi += p2 + p3;
            // store P (tf32-rounded) to warp-private slab
            float2 lo2 = make_float2(__uint_as_float(f2tf32(p0)),
                                     __uint_as_float(f2tf32(p1)));
            float2 hi2 = make_float2(__uint_as_float(f2tf32(p2)),
                                     __uint_as_float(f2tf32(p3)));
            *(float2*)&Ps[(gid    ) * SK + nt * 8 + 2 * tg] = lo2;
            *(float2*)&Ps[(gid + 8) * SK + nt * 8 + 2 * tg] = hi2;
        }
        l_lo = l_lo * corr_lo + psum_lo;
        l_hi = l_hi * corr_hi + psum_hi;

        // rescale accumulators
        #pragma unroll
        for (int nt = 0; nt < 8; ++nt) {
            oacc[nt][0] *= corr_lo; oacc[nt][1] *= corr_lo;
            oacc[nt][2] *= corr_hi; oacc[nt][3] *= corr_hi;
        }
        __syncwarp();

        // ---- O += P V ----
        #pragma unroll
        for (int kc = 0; kc < 8; ++kc) {
            uint32_t a[4];
            a[0] = __float_as_uint(Ps[(gid    ) * SK + kc * 8 + tg    ]);
            a[1] = __float_as_uint(Ps[(gid + 8) * SK + kc * 8 + tg    ]);
            a[2] = __float_as_uint(Ps[(gid    ) * SK + kc * 8 + tg + 4]);
            a[3] = __float_as_uint(Ps[(gid + 8) * SK + kc * 8 + tg + 4]);
            #pragma unroll
            for (int nt = 0; nt < 8; ++nt) {
                uint32_t b0 = __float_as_uint(Vs[(kc * 8 + tg    ) * SV + nt * 8 + gid]);
                uint32_t b1 = __float_as_uint(Vs[(kc * 8 + tg + 4) * SV + nt * 8 + gid]);
                mma_tf32(oacc[nt], a, b0, b1);
            }
        }
        __syncthreads();
    }

    // ---- finalize: reduce l across quad, normalize, write ctx ----
    l_lo += __shfl_xor_sync(0xffffffffu, l_lo, 1);
    l_lo += __shfl_xor_sync(0xffffffffu, l_lo, 2);
    l_hi += __shfl_xor_sync(0xffffffffu, l_hi, 1);
    l_hi += __shfl_xor_sync(0xffffffffu, l_hi, 2);
    float inv_lo = 1.f / l_lo;
    float inv_hi = 1.f / l_hi;

    float* out_lo = ctx + ((size_t)(b * SS + row_lo_g) * DD) + h * DKK;
    float* out_hi = ctx + ((size_t)(b * SS + row_hi_g) * DD) + h * DKK;
    #pragma unroll
    for (int nt = 0; nt < 8; ++nt) {
        *(float2*)(out_lo + nt * 8 + 2 * tg) =
            make_float2(oacc[nt][0] * inv_lo, oacc[nt][1] * inv_lo);
        *(float2*)(out_hi + nt * 8 + 2 * tg) =
            make_float2(oacc[nt][2] * inv_hi, oacc[nt][3] * inv_hi);
    }
}

// ---------------- launch ----------------
extern "C" void kernel_launch(void* const* d_in, const int* in_sizes, int n_in,
                              void* d_out, int out_size)
{
    const float* q  = (const float*)d_in[0];
    const float* k  = (const float*)d_in[1];
    const float* v  = (const float*)d_in[2];
    // d_in[3] = mask (causal tril) — implemented analytically
    const float* wq = (const float*)d_in[4];
    const float* bq = (const float*)d_in[5];
    const float* wk = (const float*)d_in[6];
    const float* bk = (const float*)d_in[7];
    const float* wv = (const float*)d_in[8];
    const float* bv = (const float*)d_in[9];
    const float* wo = (const float*)d_in[10];
    const float* bo = (const float*)d_in[11];

    float *Qp, *Kp, *Vp, *Cp;
    cudaGetSymbolAddress((void**)&Qp, g_Q);
    cudaGetSymbolAddress((void**)&Kp, g_K);
    cudaGetSymbolAddress((void**)&Vp, g_V);
    cudaGetSymbolAddress((void**)&Cp, g_ctx);

    dim3 gg(DD / 128, MROWS / 128);   // (8, 32)
    dim3 gb(256);
    gemm_tf32<true><<<gg, gb>>>(q, wq, bq, Qp);
    gemm_tf32<true><<<gg, gb>>>(k, wk, bk, Kp);
    gemm_tf32<true><<<gg, gb>>>(v, wv, bv, Vp);

    static int attn_attr_set = 0;
    if (!attn_attr_set) {
        cudaFuncSetAttribute(attn_mma, cudaFuncAttributeMaxDynamicSharedMemorySize,
                             ATTN_SMEM);
        attn_attr_set = 1;
    }
    attn_mma<<<dim3(SS / 64, BB * HH), 128, ATTN_SMEM>>>(Qp, Kp, Vp, Cp);

    gemm_tf32<false><<<gg, gb>>>(Cp, wo, bo, (float*)d_out);
}